// round 16
// baseline (speedup 1.0000x reference)
#include <cuda_runtime.h>
#include <math.h>
#include <stdint.h>

#define N_TOK 16384
#define D 512
#define VOCAB 96

// ---------------- device scratch ----------------
__device__ float4 g_V[VOCAB * D];      // (V1r, V1i, V2r, V2i) = U @ W^T
__device__ float4 g_S[VOCAB];          // (S11, S22, S12r, S12i)
__device__ float4 g_phtab[D];          // cosP, sinP, cos2P, sin2P
__device__ float4 g_cols[D];           // bias, gamma, beta, 0
__device__ float4 g_wf[N_TOK];         // wf1r, wf1i, wf2r, wf2i
__device__ float4 g_tokA[VOCAB];       // cos(cpm), sin(cpm), cos(1.3cpm), sin(1.3cpm)
__device__ float2 g_tokB[VOCAB];       // cos(.7cpm), sin(.7cpm)
// LN closed-form stats: per char, 20 floats:
// [A0..A3, G11,G22,G33,G44, G12,G13,G14,G23,G24,G34, H0..H3, B, C]
__device__ float  g_part[VOCAB * 4][20];   // per (char, q) partials
__device__ float  g_stats[VOCAB * 20];     // finalized
__device__ int    g_cnt[VOCAB / 2];        // per char-pair arrival counter (zero-init)

// ---------------- K0: fused prep — U + tables + DB GEMM + LN-stat partials ----
// grid (48, 4), 256 threads. Block (cg, q): chars {2cg, 2cg+1},
// V columns [q*128, (q+1)*128). thread = (ch = tid>>7, col = tid&127).
__global__ __launch_bounds__(256) void prep_kernel(const int* __restrict__ char_idx,
                                                   const int* __restrict__ positions,
                                                   const float* __restrict__ W,
                                                   const float* __restrict__ bias,
                                                   const float* __restrict__ gamma,
                                                   const float* __restrict__ beta_ln) {
    const int c0 = blockIdx.x * 2;
    const int q = blockIdx.y;
    const int tid = threadIdx.x;
    const int ch = tid >> 7;
    const int col = tid & 127;
    const int wid = tid >> 5;
    const int lane = tid & 31;
    const int gid = (blockIdx.y * 48 + blockIdx.x) * 256 + tid;  // 0..49151
    const float PI = 3.14159265358979323846f;
    const float TH1 = 2.0f * PI / ((float)VOCAB * (float)D);
    const float TH2 = 4.0f * PI * 1.7f / ((float)VOCAB * (float)D);

    __shared__ float4 su[2][D];       // 16 KB
    __shared__ float tile[128][33];   // ~17 KB
    __shared__ float smr[4][8];
    __shared__ float spart[8][20];
    __shared__ int isLast;

    // ---- U rows for chars c0, c0+1 ----
    #pragma unroll
    for (int l = 0; l < 2; l++) {
        const int d = tid + l * 256;
        float kv = (float)d + 1.0f;
        float s1, c1, s2, c2;
        __sincosf(1.5f * atanf(__logf(kv + 1e-10f)), &s1, &c1);
        __sincosf(0.8f * __sinf(0.1f * kv), &s2, &c2);
        float fr = 0.7f * c1 + 0.3f * c2;
        float fi = 0.7f * s1 + 0.3f * s2;
        float w1 = 0.6f + 0.4f * __sinf(0.1f * (float)d);
        float w2 = 0.4f + 0.6f * __cosf(0.15f * (float)d);
        float th1d = TH1 * (float)d;
        float th2d = TH2 * (float)d;
        #pragma unroll
        for (int cc = 0; cc < 2; cc++) {
            float s, co;
            __sincosf(th1d * (float)(c0 + cc), &s, &co);
            float u1r = w1 * (co * fr - s * fi);
            float u1i = w1 * (co * fi + s * fr);
            __sincosf(th2d * (float)(c0 + cc), &s, &co);
            float u2r = w2 * (co * fr - s * fi);
            float u2i = w2 * (co * fi + s * fr);
            su[cc][d] = make_float4(u1r, u1i, u2r, u2i);
        }
    }

    // ---- side jobs ----
    if (gid < N_TOK) {
        int ci = __ldg(&char_idx[gid]);
        float lam = (float)ci * (1.0f / (float)VOCAB);
        float t = (float)__ldg(&positions[gid]) * 0.01f;
        float omega = 2.0f * PI * 1.5f;
        float kwav = 2.0f * PI / 1.7f;
        float ph1 = omega * t - kwav * lam + 0.8f * lam * lam;
        float ph2 = omega * t * 1.5f - kwav * lam * 0.7f + 0.8f * lam * lam * 1.3f;
        float a1 = sinf(omega * t + 1.5f * lam);
        float a2 = cosf(omega * t * 0.8f + 1.5f * lam * 1.2f);
        float s, cc;
        sincosf(ph1, &s, &cc);
        float wf1r = a1 * cc, wf1i = a1 * s;
        sincosf(ph2, &s, &cc);
        float wf2r = a2 * cc, wf2i = a2 * s;
        g_wf[gid] = make_float4(wf1r, wf1i, wf2r, wf2i);
    }
    if (gid < D) {
        float ph = 2.0f * PI * (float)gid * (1.0f / (float)D);
        float sp, cp, s2p, c2p;
        __sincosf(ph, &sp, &cp);
        __sincosf(2.0f * ph, &s2p, &c2p);
        g_phtab[gid] = make_float4(cp, sp, c2p, s2p);
        g_cols[gid] = make_float4(__ldg(&bias[gid]), __ldg(&gamma[gid]),
                                  __ldg(&beta_ln[gid]), 0.f);
    }
    if (gid >= 16384 && gid < 16384 + VOCAB) {
        int cc = gid - 16384;
        float cpm = (float)cc * 0.01f;
        float s0, c0_, sb, cb, sc, ccc;
        __sincosf(cpm, &s0, &c0_);
        __sincosf(cpm * 1.3f, &sb, &cb);
        __sincosf(cpm * 0.7f, &sc, &ccc);
        g_tokA[cc] = make_float4(c0_, s0, cb, sb);
        g_tokB[cc] = make_float2(ccc, sc);
    }
    __syncthreads();

    // ---- Gram sums for norm (q == 0 blocks) ----
    if (q == 0) {
        float s11 = 0.f, s22 = 0.f, s12r = 0.f, s12i = 0.f;
        #pragma unroll
        for (int l = 0; l < 4; l++) {
            float4 u = su[ch][col + l * 128];
            s11 += u.x * u.x + u.y * u.y;
            s22 += u.z * u.z + u.w * u.w;
            s12r += u.x * u.z + u.y * u.w;
            s12i += u.y * u.z - u.x * u.w;
        }
        #pragma unroll
        for (int o = 16; o > 0; o >>= 1) {
            s11 += __shfl_xor_sync(0xffffffffu, s11, o);
            s22 += __shfl_xor_sync(0xffffffffu, s22, o);
            s12r += __shfl_xor_sync(0xffffffffu, s12r, o);
            s12i += __shfl_xor_sync(0xffffffffu, s12i, o);
        }
        if (lane == 0) {
            smr[0][wid] = s11; smr[1][wid] = s22;
            smr[2][wid] = s12r; smr[3][wid] = s12i;
        }
        __syncthreads();
        if ((tid & 127) == 0) {
            int b = ch * 4;
            g_S[c0 + ch] = make_float4(smr[0][b] + smr[0][b+1] + smr[0][b+2] + smr[0][b+3],
                                       smr[1][b] + smr[1][b+1] + smr[1][b+2] + smr[1][b+3],
                                       smr[2][b] + smr[2][b+1] + smr[2][b+2] + smr[2][b+3],
                                       smr[3][b] + smr[3][b+1] + smr[3][b+2] + smr[3][b+3]);
        }
    }

    // ---- GEMM: V[c0+ch, q*128+col], register double-buffered W tile ----
    const int dpbase = q * 128;
    float acc0 = 0.f, acc1 = 0.f, acc2 = 0.f, acc3 = 0.f;

    float4 r[4];
    #pragma unroll
    for (int l = 0; l < 4; l++) {
        int f = tid + l * 256;
        int row = f >> 3, c4 = (f & 7) * 4;
        r[l] = *(const float4*)(W + (size_t)(dpbase + row) * D + c4);
    }

    #pragma unroll 1
    for (int chunk = 0; chunk < 16; chunk++) {
        __syncthreads();
        #pragma unroll
        for (int l = 0; l < 4; l++) {
            int f = tid + l * 256;
            int row = f >> 3, c4 = (f & 7) * 4;
            tile[row][c4 + 0] = r[l].x;
            tile[row][c4 + 1] = r[l].y;
            tile[row][c4 + 2] = r[l].z;
            tile[row][c4 + 3] = r[l].w;
        }
        __syncthreads();
        if (chunk < 15) {
            #pragma unroll
            for (int l = 0; l < 4; l++) {
                int f = tid + l * 256;
                int row = f >> 3, c4 = (f & 7) * 4;
                r[l] = *(const float4*)(W + (size_t)(dpbase + row) * D
                                        + (chunk + 1) * 32 + c4);
            }
        }
        const int dk = chunk * 32;
        #pragma unroll
        for (int k = 0; k < 32; k++) {
            float wv = tile[col][k];
            float4 u = su[ch][dk + k];
            acc0 = fmaf(u.x, wv, acc0);
            acc1 = fmaf(u.y, wv, acc1);
            acc2 = fmaf(u.z, wv, acc2);
            acc3 = fmaf(u.w, wv, acc3);
        }
    }
    g_V[(c0 + ch) * D + dpbase + col] = make_float4(acc0, acc1, acc2, acc3);

    // ---- LN-stat partials over this block's 128 columns, per char ----
    {
        float bd = __ldg(&bias[dpbase + col]);
        float vals[20] = {
            acc0, acc1, acc2, acc3,
            acc0 * acc0, acc1 * acc1, acc2 * acc2, acc3 * acc3,
            acc0 * acc1, acc0 * acc2, acc0 * acc3,
            acc1 * acc2, acc1 * acc3, acc2 * acc3,
            acc0 * bd, acc1 * bd, acc2 * bd, acc3 * bd,
            bd, bd * bd
        };
        #pragma unroll
        for (int j = 0; j < 20; j++) {
            #pragma unroll
            for (int o = 16; o > 0; o >>= 1)
                vals[j] += __shfl_xor_sync(0xffffffffu, vals[j], o);
        }
        if (lane == 0) {
            #pragma unroll
            for (int j = 0; j < 20; j++) spart[wid][j] = vals[j];
        }
        __syncthreads();
        if (tid < 40) {
            int cc = tid / 20, j = tid % 20;
            int wb = cc * 4;
            float s = spart[wb][j] + spart[wb + 1][j] + spart[wb + 2][j] + spart[wb + 3][j];
            g_part[(c0 + cc) * 4 + q][j] = s;
        }
        __threadfence();
        if (tid == 0) {
            int done = atomicAdd(&g_cnt[blockIdx.x], 1);
            isLast = (done == 3) ? 1 : 0;
        }
        __syncthreads();
        if (isLast) {
            __threadfence();
            if (tid < 40) {
                int cc = tid / 20, j = tid % 20;
                float s = 0.f;
                #pragma unroll
                for (int qq = 0; qq < 4; qq++)
                    s += g_part[(c0 + cc) * 4 + qq][j];
                g_stats[(c0 + cc) * 20 + j] = s;
            }
            if (tid == 0) g_cnt[blockIdx.x] = 0;   // reset for next replay
        }
    }
}

// ---------------- K1: streaming main — no reductions, no barriers ----------
// 128-thread group processes 4 tokens sequentially; 2 groups per 256-thread block.
__global__ __launch_bounds__(256, 4) void main_kernel(const int* __restrict__ char_idx,
                                                      const float* __restrict__ noise,
                                                      const float* __restrict__ sem,
                                                      float4* __restrict__ out) {
    const int tid = threadIdx.x;
    const int grp = tid >> 7;
    const int gt = tid & 127;
    const int nbase = blockIdx.x * 8 + grp * 4;

    // register-resident per-d tables (d = k*128 + gt), loaded once for 4 tokens
    float4 colr[4], phr[4];
    #pragma unroll
    for (int k = 0; k < 4; k++) {
        colr[k] = __ldg(&g_cols[k * 128 + gt]);
        phr[k]  = __ldg(&g_phtab[k * 128 + gt]);
    }

    const float ct = 0.995004165278025766f;
    const float st = 0.0998334166468281523f;

    #pragma unroll 1
    for (int t = 0; t < 4; t++) {
        const int n = nbase + t;
        const int c = __ldg(&char_idx[n]);
        const float4 wf = __ldg(&g_wf[n]);
        const float4 S = __ldg(&g_S[c]);

        float n1 = wf.x * wf.x + wf.y * wf.y;
        float n2 = wf.z * wf.z + wf.w * wf.w;
        float Ar = wf.x * wf.z + wf.y * wf.w;
        float Ai = wf.y * wf.z - wf.x * wf.w;
        float nrm2 = n1 * S.x + n2 * S.y + 2.0f * (Ar * S.z - Ai * S.w);
        float rinv = 1.0f / (sqrtf(nrm2) + 1e-8f);
        const float p1 = (wf.x * ct - wf.y * st) * rinv;
        const float q1 = -(wf.y * ct + wf.x * st) * rinv;
        const float p2 = (wf.z * ct - wf.w * st) * rinv;
        const float q2 = -(wf.w * ct + wf.z * st) * rinv;

        // closed-form LN stats: S1 = cf·A + B ; S2 = cf'G cf + 2 cf·H + C
        const float* stp = g_stats + c * 20;
        float4 A_  = *(const float4*)(stp + 0);
        float4 Gd  = *(const float4*)(stp + 4);    // G11,G22,G33,G44
        float4 Go1 = *(const float4*)(stp + 8);    // G12,G13,G14,G23
        float4 Go2 = *(const float4*)(stp + 12);   // G24,G34,H0,H1
        float4 Ht  = *(const float4*)(stp + 16);   // H2,H3,B,C

        float S1 = p1 * A_.x + q1 * A_.y + p2 * A_.z + q2 * A_.w + Ht.z;
        float S2 = p1 * p1 * Gd.x + q1 * q1 * Gd.y + p2 * p2 * Gd.z + q2 * q2 * Gd.w
                 + 2.0f * (p1 * q1 * Go1.x + p1 * p2 * Go1.y + p1 * q2 * Go1.z
                           + q1 * p2 * Go1.w + q1 * q2 * Go2.x + p2 * q2 * Go2.y)
                 + 2.0f * (p1 * Go2.z + q1 * Go2.w + p2 * Ht.x + q2 * Ht.y)
                 + Ht.w;
        const float mu = S1 * (1.0f / (float)D);
        const float var = S2 * (1.0f / (float)D) - mu * mu;
        const float rstd = rsqrtf(var + 1e-5f);

        const float sw0 = __ldg(&sem[c * 4 + 0]);
        const float sw1 = __ldg(&sem[c * 4 + 1]);
        const float sw2 = __ldg(&sem[c * 4 + 2]);
        const float4 tA = __ldg(&g_tokA[c]);
        const float2 tB = __ldg(&g_tokB[c]);

        const float4* vrow = g_V + c * D;
        const float* nrow = noise + (size_t)n * D;
        float4* orow = out + (size_t)n * D;

        // single streaming pass: no barriers, no staging
        #pragma unroll
        for (int k = 0; k < 4; k++) {
            const int d = k * 128 + gt;
            float4 v = __ldg(&vrow[d]);
            float nz = __ldcs(&nrow[d]);
            float x = fmaf(p1, v.x, fmaf(q1, v.y, fmaf(p2, v.z, q2 * v.w))) + colr[k].x;
            float y = (x - mu) * rstd * colr[k].y + colr[k].z + 0.01f * nz;
            float4 ph = phr[k];
            float4 o;
            o.x = y;
            o.y = y * sw0 * (ph.x * tA.x - ph.y * tA.y);   // cos(phase + cpm)
            o.z = y * sw1 * (ph.y * tA.z + ph.x * tA.w);   // sin(phase + 1.3cpm)
            o.w = y * sw2 * (ph.z * tB.x - ph.w * tB.y);   // cos(2phase + 0.7cpm)
            __stcs(&orow[d], o);
        }
    }
}

// ---------------- launch ----------------
extern "C" void kernel_launch(void* const* d_in, const int* in_sizes, int n_in,
                              void* d_out, int out_size) {
    const int*   char_idx  = (const int*)d_in[0];
    const int*   positions = (const int*)d_in[1];
    const float* W         = (const float*)d_in[2];
    const float* b         = (const float*)d_in[3];
    const float* gamma     = (const float*)d_in[4];
    const float* beta_ln   = (const float*)d_in[5];
    const float* noise     = (const float*)d_in[6];
    const float* sem       = (const float*)d_in[7];
    float4* out = (float4*)d_out;

    prep_kernel<<<dim3(VOCAB / 2, 4), 256>>>(char_idx, positions, W, b, gamma, beta_ln);
    main_kernel<<<N_TOK / 8, 256>>>(char_idx, noise, sem, out);
}

// round 17
// speedup vs baseline: 1.2447x; 1.2447x over previous
#include <cuda_runtime.h>
#include <math.h>
#include <stdint.h>

#define N_TOK 16384
#define D 512
#define VOCAB 96

// ---------------- device scratch ----------------
__device__ float4 g_V[VOCAB * D];    // (V1r, V1i, V2r, V2i) = U @ W^T
__device__ float4 g_S[VOCAB];        // (S11, S22, S12r, S12i)
__device__ float4 g_phtab[D];        // cosP, sinP, cos2P, sin2P
__device__ float4 g_cols[D];         // bias, gamma, beta, 0
__device__ float4 g_wf[N_TOK];       // wf1r, wf1i, wf2r, wf2i
__device__ float4 g_tokA[VOCAB];     // cos(cpm), sin(cpm), cos(1.3cpm), sin(1.3cpm)
__device__ float2 g_tokB[VOCAB];     // cos(.7cpm), sin(.7cpm)

// ---------------- K0: fused prep — 4 chars/block, 64-col slices, DB GEMM ------
// grid (24, 8), 256 threads. Block (cg, q): chars {4cg..4cg+3},
// V columns [q*64, (q+1)*64). GEMM thread = (ch = tid>>6, col = tid&63).
__global__ __launch_bounds__(256) void prep_kernel(const int* __restrict__ char_idx,
                                                   const int* __restrict__ positions,
                                                   const float* __restrict__ W,
                                                   const float* __restrict__ bias,
                                                   const float* __restrict__ gamma,
                                                   const float* __restrict__ beta_ln) {
    const int c0 = blockIdx.x * 4;
    const int q = blockIdx.y;
    const int tid = threadIdx.x;
    const int ch = tid >> 6;        // 0..3 char within group
    const int col = tid & 63;       // column within 64-col slice
    const int wid = tid >> 5;
    const int lane = tid & 31;
    const int gid = (blockIdx.y * 24 + blockIdx.x) * 256 + tid;  // 0..49151
    const float PI = 3.14159265358979323846f;
    const float TH1 = 2.0f * PI / ((float)VOCAB * (float)D);
    const float TH2 = 4.0f * PI * 1.7f / ((float)VOCAB * (float)D);

    __shared__ float4 su[4][D];       // 32 KB
    __shared__ float tile[64][65];    // ~16.6 KB W sub-tile, padded
    __shared__ float smr[8][4];

    // ---- U rows for chars c0..c0+3 (each thread: d = tid, tid+256) ----
    #pragma unroll
    for (int l = 0; l < 2; l++) {
        const int d = tid + l * 256;
        float kv = (float)d + 1.0f;
        float s1, c1, s2, c2;
        __sincosf(1.5f * atanf(__logf(kv + 1e-10f)), &s1, &c1);
        __sincosf(0.8f * __sinf(0.1f * kv), &s2, &c2);
        float fr = 0.7f * c1 + 0.3f * c2;
        float fi = 0.7f * s1 + 0.3f * s2;
        float w1 = 0.6f + 0.4f * __sinf(0.1f * (float)d);
        float w2 = 0.4f + 0.6f * __cosf(0.15f * (float)d);
        float th1d = TH1 * (float)d;
        float th2d = TH2 * (float)d;
        #pragma unroll
        for (int cc = 0; cc < 4; cc++) {
            float s, co;
            __sincosf(th1d * (float)(c0 + cc), &s, &co);
            float u1r = w1 * (co * fr - s * fi);
            float u1i = w1 * (co * fi + s * fr);
            __sincosf(th2d * (float)(c0 + cc), &s, &co);
            float u2r = w2 * (co * fr - s * fi);
            float u2i = w2 * (co * fi + s * fr);
            su[cc][d] = make_float4(u1r, u1i, u2r, u2i);
        }
    }

    // ---- side jobs ----
    if (gid < N_TOK) {
        int ci = __ldg(&char_idx[gid]);
        float lam = (float)ci * (1.0f / (float)VOCAB);
        float t = (float)__ldg(&positions[gid]) * 0.01f;
        float omega = 2.0f * PI * 1.5f;
        float kwav = 2.0f * PI / 1.7f;
        float ph1 = omega * t - kwav * lam + 0.8f * lam * lam;
        float ph2 = omega * t * 1.5f - kwav * lam * 0.7f + 0.8f * lam * lam * 1.3f;
        float a1 = sinf(omega * t + 1.5f * lam);
        float a2 = cosf(omega * t * 0.8f + 1.5f * lam * 1.2f);
        float s, cc;
        sincosf(ph1, &s, &cc);
        float wf1r = a1 * cc, wf1i = a1 * s;
        sincosf(ph2, &s, &cc);
        float wf2r = a2 * cc, wf2i = a2 * s;
        g_wf[gid] = make_float4(wf1r, wf1i, wf2r, wf2i);
    }
    if (gid < D) {
        float ph = 2.0f * PI * (float)gid * (1.0f / (float)D);
        float sp, cp, s2p, c2p;
        __sincosf(ph, &sp, &cp);
        __sincosf(2.0f * ph, &s2p, &c2p);
        g_phtab[gid] = make_float4(cp, sp, c2p, s2p);
        g_cols[gid] = make_float4(__ldg(&bias[gid]), __ldg(&gamma[gid]),
                                  __ldg(&beta_ln[gid]), 0.f);
    }
    if (gid >= 16384 && gid < 16384 + VOCAB) {
        int cc = gid - 16384;
        float cpm = (float)cc * 0.01f;
        float s0, c0_, sb, cb, sc, ccc;
        __sincosf(cpm, &s0, &c0_);
        __sincosf(cpm * 1.3f, &sb, &cb);
        __sincosf(cpm * 0.7f, &sc, &ccc);
        g_tokA[cc] = make_float4(c0_, s0, cb, sb);
        g_tokB[cc] = make_float2(ccc, sc);
    }
    __syncthreads();

    // ---- Gram sums (q == 0 blocks): char ch handled by warps 2ch, 2ch+1 ----
    if (q == 0) {
        float s11 = 0.f, s22 = 0.f, s12r = 0.f, s12i = 0.f;
        #pragma unroll
        for (int l = 0; l < 8; l++) {
            float4 u = su[ch][col + l * 64];
            s11 += u.x * u.x + u.y * u.y;
            s22 += u.z * u.z + u.w * u.w;
            s12r += u.x * u.z + u.y * u.w;
            s12i += u.y * u.z - u.x * u.w;
        }
        #pragma unroll
        for (int o = 16; o > 0; o >>= 1) {
            s11 += __shfl_xor_sync(0xffffffffu, s11, o);
            s22 += __shfl_xor_sync(0xffffffffu, s22, o);
            s12r += __shfl_xor_sync(0xffffffffu, s12r, o);
            s12i += __shfl_xor_sync(0xffffffffu, s12i, o);
        }
        if (lane == 0) {
            smr[wid][0] = s11; smr[wid][1] = s22;
            smr[wid][2] = s12r; smr[wid][3] = s12i;
        }
        __syncthreads();
        if (tid < 4) {
            g_S[c0 + tid] = make_float4(smr[2*tid][0] + smr[2*tid+1][0],
                                        smr[2*tid][1] + smr[2*tid+1][1],
                                        smr[2*tid][2] + smr[2*tid+1][2],
                                        smr[2*tid][3] + smr[2*tid+1][3]);
        }
    }

    // ---- GEMM: V[c0+ch, q*64+col], 8 chunks of 64 k, DB W in registers ----
    const int dpbase = q * 64;
    float acc0 = 0.f, acc1 = 0.f, acc2 = 0.f, acc3 = 0.f;

    float4 r[4];
    #pragma unroll
    for (int l = 0; l < 4; l++) {          // prefetch chunk 0
        int f = tid + l * 256;             // 0..1023
        int row = f >> 4, c4 = (f & 15) * 4;
        r[l] = *(const float4*)(W + (size_t)(dpbase + row) * D + c4);
    }

    #pragma unroll 1
    for (int chunk = 0; chunk < 8; chunk++) {
        __syncthreads();
        #pragma unroll
        for (int l = 0; l < 4; l++) {
            int f = tid + l * 256;
            int row = f >> 4, c4 = (f & 15) * 4;
            tile[row][c4 + 0] = r[l].x;
            tile[row][c4 + 1] = r[l].y;
            tile[row][c4 + 2] = r[l].z;
            tile[row][c4 + 3] = r[l].w;
        }
        __syncthreads();
        if (chunk < 7) {                   // prefetch next chunk
            #pragma unroll
            for (int l = 0; l < 4; l++) {
                int f = tid + l * 256;
                int row = f >> 4, c4 = (f & 15) * 4;
                r[l] = *(const float4*)(W + (size_t)(dpbase + row) * D
                                        + (chunk + 1) * 64 + c4);
            }
        }
        const int dk = chunk * 64;
        #pragma unroll
        for (int k = 0; k < 64; k++) {
            float wv = tile[col][k];
            float4 u = su[ch][dk + k];     // warp-uniform -> broadcast
            acc0 = fmaf(u.x, wv, acc0);
            acc1 = fmaf(u.y, wv, acc1);
            acc2 = fmaf(u.z, wv, acc2);
            acc3 = fmaf(u.w, wv, acc3);
        }
    }
    g_V[(c0 + ch) * D + dpbase + col] = make_float4(acc0, acc1, acc2, acc3);
}

// ---------------- K1: fused coef + xw + LayerNorm + noise + quaternion ----------
// 128-thread group processes 8 tokens sequentially (tables amortized in regs);
// 2 groups per 256-thread block -> 16 tokens/block, grid = N_TOK/16. (R14 shape.)
__global__ __launch_bounds__(256, 4) void main_kernel(const int* __restrict__ char_idx,
                                                      const float* __restrict__ noise,
                                                      const float* __restrict__ sem,
                                                      float4* __restrict__ out) {
    __shared__ float red_s[8], red_ss[8];

    const int tid = threadIdx.x;
    const int grp = tid >> 7;
    const int gt = tid & 127;
    const int lane = tid & 31;
    const int wid = tid >> 5;
    const int nbase = blockIdx.x * 16 + grp * 8;

    float4 colr[4], phr[4];
    #pragma unroll
    for (int k = 0; k < 4; k++) {
        colr[k] = __ldg(&g_cols[k * 128 + gt]);
        phr[k]  = __ldg(&g_phtab[k * 128 + gt]);
    }

    const float ct = 0.995004165278025766f;
    const float st = 0.0998334166468281523f;

    #pragma unroll 1
    for (int t = 0; t < 8; t++) {
        const int n = nbase + t;
        const int c = __ldg(&char_idx[n]);
        const float4 wf = __ldg(&g_wf[n]);
        const float4 S = __ldg(&g_S[c]);

        float n1 = wf.x * wf.x + wf.y * wf.y;
        float n2 = wf.z * wf.z + wf.w * wf.w;
        float Ar = wf.x * wf.z + wf.y * wf.w;
        float Ai = wf.y * wf.z - wf.x * wf.w;
        float nrm2 = n1 * S.x + n2 * S.y + 2.0f * (Ar * S.z - Ai * S.w);
        float rinv = 1.0f / (sqrtf(nrm2) + 1e-8f);
        const float p1 = (wf.x * ct - wf.y * st) * rinv;
        const float q1 = -(wf.y * ct + wf.x * st) * rinv;
        const float p2 = (wf.z * ct - wf.w * st) * rinv;
        const float q2 = -(wf.w * ct + wf.z * st) * rinv;

        const float4* vrow = g_V + c * D;
        const float* nrow = noise + (size_t)n * D;
        float xw[4], nz[4];
        float s = 0.f, ss = 0.f;
        #pragma unroll
        for (int k = 0; k < 4; k++) {
            const int d = k * 128 + gt;
            float4 v = __ldg(&vrow[d]);
            nz[k] = __ldcs(&nrow[d]);
            float x = fmaf(p1, v.x, fmaf(q1, v.y, fmaf(p2, v.z, q2 * v.w))) + colr[k].x;
            xw[k] = x;
            s += x;
            ss = fmaf(x, x, ss);
        }
        #pragma unroll
        for (int o = 16; o > 0; o >>= 1) {
            s += __shfl_xor_sync(0xffffffffu, s, o);
            ss += __shfl_xor_sync(0xffffffffu, ss, o);
        }
        __syncthreads();
        if (lane == 0) { red_s[wid] = s; red_ss[wid] = ss; }
        __syncthreads();
        const int rb = grp * 4;
        float ts = red_s[rb] + red_s[rb + 1] + red_s[rb + 2] + red_s[rb + 3];
        float tss = red_ss[rb] + red_ss[rb + 1] + red_ss[rb + 2] + red_ss[rb + 3];
        const float mu = ts * (1.0f / (float)D);
        const float rstd = rsqrtf(tss * (1.0f / (float)D) - mu * mu + 1e-5f);

        const float sw0 = __ldg(&sem[c * 4 + 0]);
        const float sw1 = __ldg(&sem[c * 4 + 1]);
        const float sw2 = __ldg(&sem[c * 4 + 2]);
        const float4 tA = __ldg(&g_tokA[c]);
        const float2 tB = __ldg(&g_tokB[c]);

        float4* orow = out + (size_t)n * D;
        #pragma unroll
        for (int k = 0; k < 4; k++) {
            const int d = k * 128 + gt;
            float y = (xw[k] - mu) * rstd * colr[k].y + colr[k].z + 0.01f * nz[k];
            float4 ph = phr[k];
            float4 o;
            o.x = y;
            o.y = y * sw0 * (ph.x * tA.x - ph.y * tA.y);   // cos(phase + cpm)
            o.z = y * sw1 * (ph.y * tA.z + ph.x * tA.w);   // sin(phase + 1.3cpm)
            o.w = y * sw2 * (ph.z * tB.x - ph.w * tB.y);   // cos(2phase + 0.7cpm)
            __stcs(&orow[d], o);
        }
    }
}

// ---------------- launch ----------------
extern "C" void kernel_launch(void* const* d_in, const int* in_sizes, int n_in,
                              void* d_out, int out_size) {
    const int*   char_idx  = (const int*)d_in[0];
    const int*   positions = (const int*)d_in[1];
    const float* W         = (const float*)d_in[2];
    const float* b         = (const float*)d_in[3];
    const float* gamma     = (const float*)d_in[4];
    const float* beta_ln   = (const float*)d_in[5];
    const float* noise     = (const float*)d_in[6];
    const float* sem       = (const float*)d_in[7];
    float4* out = (float4*)d_out;

    prep_kernel<<<dim3(VOCAB / 4, 8), 256>>>(char_idx, positions, W, b, gamma, beta_ln);
    main_kernel<<<N_TOK / 16, 256>>>(char_idx, noise, sem, out);
}